// round 7
// baseline (speedup 1.0000x reference)
#include <cuda_runtime.h>

// X, Y: [64, 1, 512, 512] float32
// 3x3 separable window (w = outer(g,g), g = [WA, WB, WA]), SAME conv,
// crop [5:-5,5:-5] -> [64,502,502]; loss = sum_b mean_hw(sxx*syy - 2*sxy)
// Identity: sum(loss) = sum(sxx*syy) + 2*sum(mu_x*mu_y) - 2*sum_crop C(xy),
// where sum_crop C(xy) = sum over input pixels of A(r)*A(c)*x*y with
// A = 1 interior, A(4)=A(507)=WA, A(5)=A(506)=WA+WB (rows and cols).

#define FULLMASK 0xFFFFFFFFu
#define WA  0.30780134f
#define WB  0.38439735f
#define WAB 0.69219869f   // WA + WB

__device__ float g_part[1024];
__device__ unsigned int g_cnt = 0;

struct Row { float x[4], y[4]; };

__device__ __forceinline__ Row ldrow(const float* __restrict__ Xr,
                                     const float* __restrict__ Yr,
                                     int ib, int hb) {
    Row d;
    float2 xa = *(const float2*)(Xr + ib);   // cols j0-1, j0
    float2 xb = *(const float2*)(Xr + hb);   // cols j0+1, j0+2
    float2 ya = *(const float2*)(Yr + ib);
    float2 yb = *(const float2*)(Yr + hb);
    d.x[0]=xa.x; d.x[1]=xa.y; d.x[2]=xb.x; d.x[3]=xb.y;
    d.y[0]=ya.x; d.y[1]=ya.y; d.y[2]=yb.x; d.y[3]=yb.y;
    return d;
}

struct St {
    float Vpx[2], Vpy[2], Vpxx[2], Vpyy[2];
    float Vqx[2], Vqy[2], Vqxx[2], Vqyy[2];
    float wc0, wc1, wc2;   // xy col weights for input cols j0-1, j0, j0+1
    float mk[2], mk2[2];   // output-col masks (and 2x)
    float accP, accC;
};

__device__ __forceinline__ void htap(const Row& d, float hx[2], float hy[2],
                                     float hxx[2], float hyy[2]) {
    float q[4], r[4];
#pragma unroll
    for (int k = 0; k < 4; k++) { q[k] = d.x[k] * d.x[k]; r[k] = d.y[k] * d.y[k]; }
#pragma unroll
    for (int k = 0; k < 2; k++) {
        hx[k]  = fmaf(WA, d.x[k], fmaf(WB, d.x[k+1], WA * d.x[k+2]));
        hy[k]  = fmaf(WA, d.y[k], fmaf(WB, d.y[k+1], WA * d.y[k+2]));
        hxx[k] = fmaf(WA, q[k],   fmaf(WB, q[k+1],   WA * q[k+2]));
        hyy[k] = fmaf(WA, r[k],   fmaf(WB, r[k+1],   WA * r[k+2]));
    }
}

// branch-free xy row term: accC += rwm2 * sum_c wc_c * x_c * y_c
__device__ __forceinline__ void xyrow(const Row& d, St& st, float rwm2) {
    float rxy =       st.wc0 * (d.x[0] * d.y[0]);
    rxy = fmaf(st.wc1, d.x[1] * d.y[1], rxy);
    rxy = fmaf(st.wc2, d.x[2] * d.y[2], rxy);
    st.accC = fmaf(rwm2, rxy, st.accC);
}

// finish output row (Vp + WA*h), accumulate loss terms, roll Vp/Vq
__device__ __forceinline__ void vstep(const Row& d, St& st, float rwm2) {
    float hx[2], hy[2], hxx[2], hyy[2];
    htap(d, hx, hy, hxx, hyy);
    xyrow(d, st, rwm2);
#pragma unroll
    for (int k = 0; k < 2; k++) {
        float vx  = fmaf(WA, hx[k],  st.Vpx[k]);
        float vy  = fmaf(WA, hy[k],  st.Vpy[k]);
        float vxx = fmaf(WA, hxx[k], st.Vpxx[k]);
        float vyy = fmaf(WA, hyy[k], st.Vpyy[k]);
        float sxx = fmaf(-vx, vx, vxx);
        float syy = fmaf(-vy, vy, vyy);
        st.accP = fmaf(st.mk[k],  sxx * syy, st.accP);
        st.accC = fmaf(st.mk2[k], vx * vy,   st.accC);
        st.Vpx[k]  = fmaf(WB, hx[k],  st.Vqx[k]);   st.Vqx[k]  = WA * hx[k];
        st.Vpy[k]  = fmaf(WB, hy[k],  st.Vqy[k]);   st.Vqy[k]  = WA * hy[k];
        st.Vpxx[k] = fmaf(WB, hxx[k], st.Vqxx[k]);  st.Vqxx[k] = WA * hxx[k];
        st.Vpyy[k] = fmaf(WB, hyy[k], st.Vqyy[k]);  st.Vqyy[k] = WA * hyy[k];
    }
}

__device__ __forceinline__ float colW(int c) {
    if (c > 507) return 0.0f;
    if (c == 5 || c == 506) return WAB;
    if (c == 507) return WA;
    return 1.0f;
}

__global__ void __launch_bounds__(128, 6)
loss_kernel(const float* __restrict__ X, const float* __restrict__ Y,
            float* __restrict__ out) {
    const int lane = threadIdx.x & 31;
    const int wid  = threadIdx.x >> 5;
    const int unit = blockIdx.x * 4 + wid;   // 4096 warp units
    const int b = unit >> 6;                 // image
    const int s = (unit >> 3) & 7;           // col stripe (64 output cols)
    const int t = unit & 7;                  // row strip (64 output rows)

    const int r0   = 5 + 64 * t;
    const int rend = min(r0 + 64, 507);      // last input row of strip
    const bool t0 = (t == 0), tl = (t == 7);

    const int j0 = 5 + 64 * s + 2 * lane;    // first of 2 output cols
    const int ib = min(j0 - 1, 508);         // aligned float2 bases (even)
    const int hb = min(j0 + 1, 510);

    const float* xp = X + ((size_t)b << 18) + (size_t)(r0 - 1) * 512;
    const float* yp = Y + ((size_t)b << 18) + (size_t)(r0 - 1) * 512;

    St st;
    st.accP = 0.0f; st.accC = 0.0f;
    st.wc0 = (j0 == 5) ? WA : 0.0f;          // input col 4 (leftmost lane only)
    st.wc1 = colW(j0);
    st.wc2 = colW(j0 + 1);
    st.mk[0]  = (j0     <= 506) ? 1.0f : 0.0f;
    st.mk[1]  = (j0 + 1 <= 506) ? 1.0f : 0.0f;
    st.mk2[0] = 2.0f * st.mk[0];
    st.mk2[1] = 2.0f * st.mk[1];

    // ---- prime: row r0-1 seeds Vq; xy weight A(r0-1)
    Row cur = ldrow(xp, yp, ib, hb);
    {
        float hx[2], hy[2], hxx[2], hyy[2];
        htap(cur, hx, hy, hxx, hyy);
        xyrow(cur, st, t0 ? -2.0f * WA : -2.0f);
#pragma unroll
        for (int k = 0; k < 2; k++) {
            st.Vqx[k]  = WA * hx[k];   st.Vqy[k]  = WA * hy[k];
            st.Vqxx[k] = WA * hxx[k];  st.Vqyy[k] = WA * hyy[k];
        }
    }
    xp += 512; yp += 512;
    // ---- prime: row r0 -> Vp for output row r0; xy weight A(r0)
    cur = ldrow(xp, yp, ib, hb);
    {
        float hx[2], hy[2], hxx[2], hyy[2];
        htap(cur, hx, hy, hxx, hyy);
        xyrow(cur, st, t0 ? -2.0f * WAB : -2.0f);
#pragma unroll
        for (int k = 0; k < 2; k++) {
            st.Vpx[k]  = fmaf(WB, hx[k],  st.Vqx[k]);   st.Vqx[k]  = WA * hx[k];
            st.Vpy[k]  = fmaf(WB, hy[k],  st.Vqy[k]);   st.Vqy[k]  = WA * hy[k];
            st.Vpxx[k] = fmaf(WB, hxx[k], st.Vqxx[k]);  st.Vqxx[k] = WA * hxx[k];
            st.Vpyy[k] = fmaf(WB, hyy[k], st.Vqyy[k]);  st.Vqyy[k] = WA * hyy[k];
        }
    }

    // ---- 2-deep pipeline: hold rows i+1, i+2 while finishing row i
    cur     = ldrow(xp + 512,  yp + 512,  ib, hb);   // row r0+1
    Row nx1 = ldrow(xp + 1024, yp + 1024, ib, hb);   // row r0+2
    xp += 1536; yp += 1536;                           // -> row r0+3

    // main loop: vstep rows r0+1 .. rend-2 (xy weight 1, compile-time);
    // body loads row i+2 (<= rend <= 507, always in-bounds)
#pragma unroll 2
    for (int i = r0 + 1; i <= rend - 2; ++i) {
        Row nx2 = ldrow(xp, yp, ib, hb);
        xp += 512; yp += 512;
        vstep(cur, st, -2.0f);
        cur = nx1; nx1 = nx2;
    }
    // ---- peeled tails: rows rend-1, rend (xy rim rows owned by last strip)
    vstep(cur, st, tl ? -2.0f * WAB : 0.0f);          // row rend-1 (506 if tl)
    vstep(nx1, st, tl ? -2.0f * WA  : 0.0f);          // row rend   (507 if tl)

    // warp -> block -> grid reduction (last block finalizes)
    float acs = st.accP + st.accC;
#pragma unroll
    for (int o = 16; o > 0; o >>= 1) acs += __shfl_xor_sync(FULLMASK, acs, o);

    __shared__ float sp[4];
    __shared__ bool is_last;
    __shared__ double sh[128];
    if (lane == 0) sp[wid] = acs;
    __syncthreads();
    if (threadIdx.x == 0) {
        g_part[blockIdx.x] = (sp[0] + sp[1]) + (sp[2] + sp[3]);
        __threadfence();
        unsigned r = atomicAdd(&g_cnt, 1u);
        is_last = (r == gridDim.x - 1);
    }
    __syncthreads();
    if (is_last) {
        __threadfence();
        double ds = 0.0;
#pragma unroll
        for (int i = threadIdx.x; i < 1024; i += 128) ds += (double)g_part[i];
        sh[threadIdx.x] = ds;
        __syncthreads();
        for (int o = 64; o > 0; o >>= 1) {
            if (threadIdx.x < o) sh[threadIdx.x] += sh[threadIdx.x + o];
            __syncthreads();
        }
        if (threadIdx.x == 0) {
            out[0] = (float)(sh[0] * (1.0 / 252004.0));
            g_cnt = 0;   // reset for next graph replay (deterministic)
        }
    }
}

extern "C" void kernel_launch(void* const* d_in, const int* in_sizes, int n_in,
                              void* d_out, int out_size) {
    const float* X = (const float*)d_in[0];
    const float* Y = (const float*)d_in[1];
    float* out = (float*)d_out;

    // 4096 warps = 64 images x 8 col-stripes(64) x 8 row-strips(64); 4/block
    loss_kernel<<<1024, 128>>>(X, Y, out);
}

// round 8
// speedup vs baseline: 1.2419x; 1.2419x over previous
#include <cuda_runtime.h>
#include <cstdint>

// X, Y: [64, 1, 512, 512] float32
// 3x3 separable window (w = outer(g,g), g = [WA, WB, WA]), SAME conv,
// crop [5:-5,5:-5] -> [64,502,502]; loss = sum_b mean_hw(sxx*syy - 2*sxy)
// Identity: sum(loss) = sum(sxx*syy) + 2*sum(mu_x*mu_y) - 2*sum_crop C(xy),
// where sum_crop C(xy) = sum over input pixels of A(r)*A(c)*x*y with
// A = 1 interior, A(4)=A(507)=WA, A(5)=A(506)=WA+WB (rows and cols).

#define FULLMASK 0xFFFFFFFFu
#define WA  0.30780134f
#define WB  0.38439735f
#define WAB 0.69219869f   // WA + WB

#define NS      8         // smem ring stages per warp
#define DEPTH   6         // cp.async prefetch distance (committed groups in flight)
#define STAGE_B 544       // bytes per stage: X[68 floats]=272 + Y[68 floats]=272
#define WARP_B  (NS * STAGE_B)

__device__ float g_part[1024];
__device__ unsigned int g_cnt = 0;

struct Row { float x[4], y[4]; };

struct St {
    float Vpx[2], Vpy[2], Vpxx[2], Vpyy[2];
    float Vqx[2], Vqy[2], Vqxx[2], Vqyy[2];
    float wc0, wc1, wc2;   // xy col weights for input cols j0-1, j0, j0+1
    float mk[2], mk2[2];   // output-col masks (and 2x)
    float accP, accC;
};

__device__ __forceinline__ void htap(const Row& d, float hx[2], float hy[2],
                                     float hxx[2], float hyy[2]) {
    float q[4], r[4];
#pragma unroll
    for (int k = 0; k < 4; k++) { q[k] = d.x[k] * d.x[k]; r[k] = d.y[k] * d.y[k]; }
#pragma unroll
    for (int k = 0; k < 2; k++) {
        hx[k]  = fmaf(WA, d.x[k], fmaf(WB, d.x[k+1], WA * d.x[k+2]));
        hy[k]  = fmaf(WA, d.y[k], fmaf(WB, d.y[k+1], WA * d.y[k+2]));
        hxx[k] = fmaf(WA, q[k],   fmaf(WB, q[k+1],   WA * q[k+2]));
        hyy[k] = fmaf(WA, r[k],   fmaf(WB, r[k+1],   WA * r[k+2]));
    }
}

__device__ __forceinline__ void xyrow(const Row& d, St& st, float rwm2) {
    float rxy =       st.wc0 * (d.x[0] * d.y[0]);
    rxy = fmaf(st.wc1, d.x[1] * d.y[1], rxy);
    rxy = fmaf(st.wc2, d.x[2] * d.y[2], rxy);
    st.accC = fmaf(rwm2, rxy, st.accC);
}

__device__ __forceinline__ void vstep(const Row& d, St& st, float rwm2) {
    float hx[2], hy[2], hxx[2], hyy[2];
    htap(d, hx, hy, hxx, hyy);
    xyrow(d, st, rwm2);
#pragma unroll
    for (int k = 0; k < 2; k++) {
        float vx  = fmaf(WA, hx[k],  st.Vpx[k]);
        float vy  = fmaf(WA, hy[k],  st.Vpy[k]);
        float vxx = fmaf(WA, hxx[k], st.Vpxx[k]);
        float vyy = fmaf(WA, hyy[k], st.Vpyy[k]);
        float sxx = fmaf(-vx, vx, vxx);
        float syy = fmaf(-vy, vy, vyy);
        st.accP = fmaf(st.mk[k],  sxx * syy, st.accP);
        st.accC = fmaf(st.mk2[k], vx * vy,   st.accC);
        st.Vpx[k]  = fmaf(WB, hx[k],  st.Vqx[k]);   st.Vqx[k]  = WA * hx[k];
        st.Vpy[k]  = fmaf(WB, hy[k],  st.Vqy[k]);   st.Vqy[k]  = WA * hy[k];
        st.Vpxx[k] = fmaf(WB, hxx[k], st.Vqxx[k]);  st.Vqxx[k] = WA * hxx[k];
        st.Vpyy[k] = fmaf(WB, hyy[k], st.Vqyy[k]);  st.Vqyy[k] = WA * hyy[k];
    }
}

__device__ __forceinline__ float colW(int c) {
    if (c > 507) return 0.0f;
    if (c == 5 || c == 506) return WAB;
    if (c == 507) return WA;
    return 1.0f;
}

__global__ void __launch_bounds__(128, 7)
loss_kernel(const float* __restrict__ X, const float* __restrict__ Y,
            float* __restrict__ out) {
    const int lane = threadIdx.x & 31;
    const int wid  = threadIdx.x >> 5;
    const int unit = blockIdx.x * 4 + wid;   // 4096 warp units
    const int b = unit >> 6;                 // image
    const int s = (unit >> 3) & 7;           // col stripe (64 output cols)
    const int t = unit & 7;                  // row strip (64 output rows)

    const int r0   = 5 + 64 * t;
    const int rend = min(r0 + 64, 507);      // last input row of strip
    const bool t0 = (t == 0), tl = (t == 7);

    const int j0    = 5 + 64 * s + 2 * lane; // first of 2 output cols
    const int cbase = 4 + 64 * s;            // smem slot-0 global col (16B aligned)

    const float* Xb = X + ((size_t)b << 18);
    const float* Yb = Y + ((size_t)b << 18);

    __shared__ __align__(16) char sbuf[4 * WARP_B];
    char* wbuf = sbuf + wid * WARP_B;
    const uint32_t wsa = (uint32_t)__cvta_generic_to_shared(wbuf);

    St st;
    st.accP = 0.0f; st.accC = 0.0f;
    st.wc0 = (j0 == 5) ? WA : 0.0f;          // input col 4 (leftmost lane only)
    st.wc1 = colW(j0);
    st.wc2 = colW(j0 + 1);
    st.mk[0]  = (j0     <= 506) ? 1.0f : 0.0f;
    st.mk[1]  = (j0 + 1 <= 506) ? 1.0f : 0.0f;
    st.mk2[0] = 2.0f * st.mk[0];
    st.mk2[1] = 2.0f * st.mk[1];

    // ---- producer: cp.async one input row (X+Y, 68 floats each) into stage sg
    auto issue = [&](int row, int sg) {
        const float* gx = Xb + (size_t)row * 512 + cbase + 4 * lane;
        const float* gy = Yb + (size_t)row * 512 + cbase + 4 * lane;
        uint32_t dx = wsa + sg * STAGE_B + lane * 16;
        asm volatile(
            "{\n\t.reg .pred p;\n\t"
            "setp.lt.u32 p, %0, 17;\n\t"
            "@p cp.async.cg.shared.global [%1], [%2], 16;\n\t"
            "@p cp.async.cg.shared.global [%3], [%4], 16;\n\t}"
            :: "r"((uint32_t)lane), "r"(dx), "l"(gx), "r"(dx + 272), "l"(gy));
        asm volatile("cp.async.commit_group;" ::: "memory");
    };
    // ---- consumer: wait oldest stage, read lane's 4+4 floats
    auto fetch = [&](int sg, Row& d) {
        asm volatile("cp.async.wait_group %0;" :: "n"(DEPTH - 1) : "memory");
        __syncwarp();
        const float2* px = (const float2*)(wbuf + sg * STAGE_B + lane * 8);
        const float2* py = (const float2*)(wbuf + sg * STAGE_B + 272 + lane * 8);
        float2 x01 = px[0], x23 = px[1];
        float2 y01 = py[0], y23 = py[1];
        d.x[0]=x01.x; d.x[1]=x01.y; d.x[2]=x23.x; d.x[3]=x23.y;
        d.y[0]=y01.x; d.y[1]=y01.y; d.y[2]=y23.x; d.y[3]=y23.y;
    };

    // prologue: fill DEPTH stages (rows r0-1 .. r0-1+DEPTH-1, clamped)
#pragma unroll
    for (int p = 0; p < DEPTH; ++p) issue(min(r0 - 1 + p, 507), p);

    int cons = 0;   // row r0-1+cons is the next consumed
    Row d;

    // ---- prime: row r0-1 seeds Vq; xy weight A(r0-1)
    fetch(cons & (NS - 1), d);
    issue(min(r0 - 1 + cons + DEPTH, 507), (cons + DEPTH) & (NS - 1));
    {
        float hx[2], hy[2], hxx[2], hyy[2];
        htap(d, hx, hy, hxx, hyy);
        xyrow(d, st, t0 ? -2.0f * WA : -2.0f);
#pragma unroll
        for (int k = 0; k < 2; k++) {
            st.Vqx[k]  = WA * hx[k];   st.Vqy[k]  = WA * hy[k];
            st.Vqxx[k] = WA * hxx[k];  st.Vqyy[k] = WA * hyy[k];
        }
    }
    ++cons;
    // ---- prime: row r0 -> Vp for output row r0; xy weight A(r0)
    fetch(cons & (NS - 1), d);
    issue(min(r0 - 1 + cons + DEPTH, 507), (cons + DEPTH) & (NS - 1));
    {
        float hx[2], hy[2], hxx[2], hyy[2];
        htap(d, hx, hy, hxx, hyy);
        xyrow(d, st, t0 ? -2.0f * WAB : -2.0f);
#pragma unroll
        for (int k = 0; k < 2; k++) {
            st.Vpx[k]  = fmaf(WB, hx[k],  st.Vqx[k]);   st.Vqx[k]  = WA * hx[k];
            st.Vpy[k]  = fmaf(WB, hy[k],  st.Vqy[k]);   st.Vqy[k]  = WA * hy[k];
            st.Vpxx[k] = fmaf(WB, hxx[k], st.Vqxx[k]);  st.Vqxx[k] = WA * hxx[k];
            st.Vpyy[k] = fmaf(WB, hyy[k], st.Vqyy[k]);  st.Vqyy[k] = WA * hyy[k];
        }
    }
    ++cons;

    // ---- main loop: rows r0+1 .. rend-2, xy weight 1 (compile-time constant)
    for (int i = r0 + 1; i <= rend - 2; ++i, ++cons) {
        fetch(cons & (NS - 1), d);
        issue(min(r0 - 1 + cons + DEPTH, 507), (cons + DEPTH) & (NS - 1));
        vstep(d, st, -2.0f);
    }
    // ---- peeled tails: rows rend-1, rend (xy rim rows owned by last strip)
    fetch(cons & (NS - 1), d);
    issue(min(r0 - 1 + cons + DEPTH, 507), (cons + DEPTH) & (NS - 1));
    vstep(d, st, tl ? -2.0f * WAB : 0.0f);       // row rend-1 (506 if tl)
    ++cons;
    fetch(cons & (NS - 1), d);
    issue(min(r0 - 1 + cons + DEPTH, 507), (cons + DEPTH) & (NS - 1));
    vstep(d, st, tl ? -2.0f * WA : 0.0f);        // row rend   (507 if tl)
    asm volatile("cp.async.wait_group 0;" ::: "memory");  // drain before exit

    // warp -> block -> grid reduction (last block finalizes)
    float acs = st.accP + st.accC;
#pragma unroll
    for (int o = 16; o > 0; o >>= 1) acs += __shfl_xor_sync(FULLMASK, acs, o);

    __shared__ float sp[4];
    __shared__ bool is_last;
    __shared__ double sh[128];
    if (lane == 0) sp[wid] = acs;
    __syncthreads();
    if (threadIdx.x == 0) {
        g_part[blockIdx.x] = (sp[0] + sp[1]) + (sp[2] + sp[3]);
        __threadfence();
        unsigned r = atomicAdd(&g_cnt, 1u);
        is_last = (r == gridDim.x - 1);
    }
    __syncthreads();
    if (is_last) {
        __threadfence();
        double ds = 0.0;
#pragma unroll
        for (int i = threadIdx.x; i < 1024; i += 128) ds += (double)g_part[i];
        sh[threadIdx.x] = ds;
        __syncthreads();
        for (int o = 64; o > 0; o >>= 1) {
            if (threadIdx.x < o) sh[threadIdx.x] += sh[threadIdx.x + o];
            __syncthreads();
        }
        if (threadIdx.x == 0) {
            out[0] = (float)(sh[0] * (1.0 / 252004.0));
            g_cnt = 0;   // reset for next graph replay (deterministic)
        }
    }
}

extern "C" void kernel_launch(void* const* d_in, const int* in_sizes, int n_in,
                              void* d_out, int out_size) {
    const float* X = (const float*)d_in[0];
    const float* Y = (const float*)d_in[1];
    float* out = (float*)d_out;

    // 4096 warps = 64 images x 8 col-stripes(64) x 8 row-strips(64); 4/block
    loss_kernel<<<1024, 128>>>(X, Y, out);
}

// round 9
// speedup vs baseline: 1.3205x; 1.0633x over previous
#include <cuda_runtime.h>
#include <cstdint>

// X, Y: [64, 1, 512, 512] float32
// 3x3 separable window (w = outer(g,g), g = [WA, WB, WA]), SAME conv,
// crop [5:-5,5:-5] -> [64,502,502]; loss = sum_b mean_hw(sxx*syy - 2*sxy)
// Identity: sum(loss) = sum(sxx*syy) + 2*sum(mu_x*mu_y) - 2*sum_rim A(r)A(c)xy
// A = 1 interior, A(4)=A(507)=WA, A(5)=A(506)=WA+WB (rows and cols).

#define FULLMASK 0xFFFFFFFFu
#define WA  0.30780134f
#define WB  0.38439735f
#define WAB 0.69219869f   // WA + WB

#define NS       6        // smem ring stages per warp
#define DEPTH    5        // cp.async prefetch distance
#define STAGE_F  136      // floats per array per stage (128 cols + halo + pad)
#define STAGE_FT (2 * STAGE_F)   // X + Y = 272 floats per stage

__device__ float g_part[1024];
__device__ unsigned int g_cnt = 0;

struct St {
    float Vpx[4], Vpy[4], Vpxx[4], Vpyy[4];
    float Vqx[4], Vqy[4], Vqxx[4], Vqyy[4];
    float wc[5];           // xy col weights for input cols j0-1 .. j0+3
    float mk[4];           // output-col masks
    float accP, accMU, accXY;
};

__device__ __forceinline__ float colW(int c) {
    if (c > 507) return 0.0f;
    if (c == 5 || c == 506) return WAB;
    if (c == 507) return WA;
    return 1.0f;
}

// finish output row (Vp + WA*h), accumulate terms, roll Vp/Vq.
// rw = xy row weight (0 if row not owned). x[6], y[6] = input cols j0-1..j0+4.
__device__ __forceinline__ void vstep(const float x[6], const float y[6],
                                      St& st, float rw) {
    float q[6], r[6];
#pragma unroll
    for (int k = 0; k < 6; k++) { q[k] = x[k] * x[k]; r[k] = y[k] * y[k]; }
    // xy rim/interior term (input cols j0-1 .. j0+3)
    float rxy =        st.wc[0] * (x[0] * y[0]);
    rxy = fmaf(st.wc[1], x[1] * y[1], rxy);
    rxy = fmaf(st.wc[2], x[2] * y[2], rxy);
    rxy = fmaf(st.wc[3], x[3] * y[3], rxy);
    rxy = fmaf(st.wc[4], x[4] * y[4], rxy);
    st.accXY = fmaf(rw, rxy, st.accXY);
#pragma unroll
    for (int k = 0; k < 4; k++) {
        float hx  = fmaf(WA, x[k], fmaf(WB, x[k+1], WA * x[k+2]));
        float hy  = fmaf(WA, y[k], fmaf(WB, y[k+1], WA * y[k+2]));
        float hxx = fmaf(WA, q[k], fmaf(WB, q[k+1], WA * q[k+2]));
        float hyy = fmaf(WA, r[k], fmaf(WB, r[k+1], WA * r[k+2]));
        float vx  = fmaf(WA, hx,  st.Vpx[k]);
        float vy  = fmaf(WA, hy,  st.Vpy[k]);
        float vxx = fmaf(WA, hxx, st.Vpxx[k]);
        float vyy = fmaf(WA, hyy, st.Vpyy[k]);
        float sxx = fmaf(-vx, vx, vxx);
        float syy = fmaf(-vy, vy, vyy);
        st.accP  = fmaf(st.mk[k], sxx * syy, st.accP);
        st.accMU = fmaf(st.mk[k], vx * vy,   st.accMU);
        st.Vpx[k]  = fmaf(WB, hx,  st.Vqx[k]);   st.Vqx[k]  = WA * hx;
        st.Vpy[k]  = fmaf(WB, hy,  st.Vqy[k]);   st.Vqy[k]  = WA * hy;
        st.Vpxx[k] = fmaf(WB, hxx, st.Vqxx[k]);  st.Vqxx[k] = WA * hxx;
        st.Vpyy[k] = fmaf(WB, hyy, st.Vqyy[k]);  st.Vqyy[k] = WA * hyy;
    }
}

__global__ void __launch_bounds__(128, 6)
loss_kernel(const float* __restrict__ X, const float* __restrict__ Y,
            float* __restrict__ out) {
    const int lane = threadIdx.x & 31;
    const int wid  = threadIdx.x >> 5;
    const int unit = blockIdx.x * 4 + wid;   // 4096 warp units
    const int b = unit >> 6;                 // image
    const int s = (unit >> 4) & 3;           // col stripe (128 output cols)
    const int t = unit & 15;                 // row strip (32 output rows)

    const int r0   = 5 + 32 * t;
    const int rend = min(r0 + 32, 507);      // last input row of strip
    const bool t0 = (t == 0), tl = (t == 15);

    const int j0    = 5 + 128 * s + 4 * lane;  // first of 4 output cols
    const int cbase = 4 + 128 * s;             // smem col-0 global col

    const float* Xb = X + ((size_t)b << 18);
    const float* Yb = Y + ((size_t)b << 18);

    __shared__ __align__(16) float sbuf[4 * NS * STAGE_FT];
    float* wbuf = sbuf + wid * NS * STAGE_FT;
    const uint32_t wsa = (uint32_t)__cvta_generic_to_shared(wbuf);

    St st;
    st.accP = 0.0f; st.accMU = 0.0f; st.accXY = 0.0f;
    st.wc[0] = (j0 == 5) ? WA : 0.0f;        // input col 4 (leftmost lane only)
#pragma unroll
    for (int k = 0; k < 4; k++) {
        st.wc[k + 1] = colW(j0 + k);
        st.mk[k]     = (j0 + k <= 506) ? 1.0f : 0.0f;
    }

    // producer: copy one input row (X,Y: 136 floats each) into stage sg.
    // lanes 0..16 each copy 32B per array (2 x 16B cp.async).
    auto issue = [&](int row, int sg) {
        const float* gx = Xb + (size_t)row * 512 + cbase + 8 * lane;
        const float* gy = Yb + (size_t)row * 512 + cbase + 8 * lane;
        uint32_t dx = wsa + (sg * STAGE_FT + 8 * lane) * 4;
        asm volatile(
            "{\n\t.reg .pred p;\n\t"
            "setp.lt.u32 p, %0, 17;\n\t"
            "@p cp.async.cg.shared.global [%1], [%2], 16;\n\t"
            "@p cp.async.cg.shared.global [%3], [%4], 16;\n\t"
            "@p cp.async.cg.shared.global [%5], [%6], 16;\n\t"
            "@p cp.async.cg.shared.global [%7], [%8], 16;\n\t}"
            :: "r"((uint32_t)lane),
               "r"(dx),                       "l"(gx),
               "r"(dx + 16),                  "l"(gx + 4),
               "r"(dx + STAGE_F * 4),         "l"(gy),
               "r"(dx + STAGE_F * 4 + 16),    "l"(gy + 4));
        asm volatile("cp.async.commit_group;" ::: "memory");
    };
    // consumer: wait oldest stage, read lane's 6+6 floats
    auto fetch = [&](int sg, float x[6], float y[6]) {
        asm volatile("cp.async.wait_group %0;" :: "n"(DEPTH - 1) : "memory");
        __syncwarp();
        const float* px = wbuf + sg * STAGE_FT + 4 * lane;
        const float* py = px + STAGE_F;
        float4 xa = *(const float4*)px;  float2 xb2 = *(const float2*)(px + 4);
        float4 ya = *(const float4*)py;  float2 yb2 = *(const float2*)(py + 4);
        x[0]=xa.x; x[1]=xa.y; x[2]=xa.z; x[3]=xa.w; x[4]=xb2.x; x[5]=xb2.y;
        y[0]=ya.x; y[1]=ya.y; y[2]=ya.z; y[3]=ya.w; y[4]=yb2.x; y[5]=yb2.y;
    };

    int sg = 0;   // ring slot of next consumed row; rows consumed in order
#pragma unroll
    for (int p = 0; p < DEPTH; ++p) issue(min(r0 - 1 + p, 507), p);
    int nrow = r0 - 1 + DEPTH;   // next row to issue
    int nsg  = DEPTH;            // its slot

    float x[6], y[6];

    // ---- prime: row r0-1 seeds Vq; xy row weight A(r0-1)
    fetch(sg, x, y);
    issue(min(nrow, 507), nsg % NS);
    ++nrow; ++nsg; sg = (sg + 1) % NS;
    {
        float q[6], r[6];
#pragma unroll
        for (int k = 0; k < 6; k++) { q[k] = x[k]*x[k]; r[k] = y[k]*y[k]; }
        float rxy =        st.wc[0] * (x[0] * y[0]);
        rxy = fmaf(st.wc[1], x[1] * y[1], rxy);
        rxy = fmaf(st.wc[2], x[2] * y[2], rxy);
        rxy = fmaf(st.wc[3], x[3] * y[3], rxy);
        rxy = fmaf(st.wc[4], x[4] * y[4], rxy);
        st.accXY = fmaf(t0 ? WA : 1.0f, rxy, st.accXY);
#pragma unroll
        for (int k = 0; k < 4; k++) {
            st.Vqx[k]  = WA * fmaf(WA, x[k], fmaf(WB, x[k+1], WA * x[k+2]));
            st.Vqy[k]  = WA * fmaf(WA, y[k], fmaf(WB, y[k+1], WA * y[k+2]));
            st.Vqxx[k] = WA * fmaf(WA, q[k], fmaf(WB, q[k+1], WA * q[k+2]));
            st.Vqyy[k] = WA * fmaf(WA, r[k], fmaf(WB, r[k+1], WA * r[k+2]));
        }
    }
    // ---- prime: row r0 -> Vp for output row r0; xy row weight A(r0)
    fetch(sg, x, y);
    issue(min(nrow, 507), nsg % NS);
    ++nrow; ++nsg; sg = (sg + 1) % NS;
    {
        float q[6], r[6];
#pragma unroll
        for (int k = 0; k < 6; k++) { q[k] = x[k]*x[k]; r[k] = y[k]*y[k]; }
        float rxy =        st.wc[0] * (x[0] * y[0]);
        rxy = fmaf(st.wc[1], x[1] * y[1], rxy);
        rxy = fmaf(st.wc[2], x[2] * y[2], rxy);
        rxy = fmaf(st.wc[3], x[3] * y[3], rxy);
        rxy = fmaf(st.wc[4], x[4] * y[4], rxy);
        st.accXY = fmaf(t0 ? WAB : 1.0f, rxy, st.accXY);
#pragma unroll
        for (int k = 0; k < 4; k++) {
            float hx  = fmaf(WA, x[k], fmaf(WB, x[k+1], WA * x[k+2]));
            float hy  = fmaf(WA, y[k], fmaf(WB, y[k+1], WA * y[k+2]));
            float hxx = fmaf(WA, q[k], fmaf(WB, q[k+1], WA * q[k+2]));
            float hyy = fmaf(WA, r[k], fmaf(WB, r[k+1], WA * r[k+2]));
            st.Vpx[k]  = fmaf(WB, hx,  st.Vqx[k]);   st.Vqx[k]  = WA * hx;
            st.Vpy[k]  = fmaf(WB, hy,  st.Vqy[k]);   st.Vqy[k]  = WA * hy;
            st.Vpxx[k] = fmaf(WB, hxx, st.Vqxx[k]);  st.Vqxx[k] = WA * hxx;
            st.Vpyy[k] = fmaf(WB, hyy, st.Vqyy[k]);  st.Vqyy[k] = WA * hyy;
        }
    }

    // ---- main loop: rows r0+1 .. rend-2, xy row weight 1 (constant)
    for (int i = r0 + 1; i <= rend - 2; ++i) {
        fetch(sg, x, y);
        issue(min(nrow, 507), nsg % NS);
        ++nrow; ++nsg; sg = (sg + 1) % NS;
        vstep(x, y, st, 1.0f);
    }
    // ---- peeled tails: rows rend-1, rend (xy rim rows owned by last strip)
    fetch(sg, x, y);
    issue(min(nrow, 507), nsg % NS);
    ++nsg; sg = (sg + 1) % NS;
    vstep(x, y, st, tl ? WAB : 0.0f);        // row rend-1 (506 if tl)
    fetch(sg, x, y);
    vstep(x, y, st, tl ? WA : 0.0f);         // row rend   (507 if tl)
    asm volatile("cp.async.wait_group 0;" ::: "memory");  // drain before exit

    // warp -> block -> grid reduction (last block finalizes)
    float acs = st.accP + 2.0f * (st.accMU - st.accXY);
#pragma unroll
    for (int o = 16; o > 0; o >>= 1) acs += __shfl_xor_sync(FULLMASK, acs, o);

    __shared__ float sp[4];
    __shared__ bool is_last;
    __shared__ double sh[128];
    if (lane == 0) sp[wid] = acs;
    __syncthreads();
    if (threadIdx.x == 0) {
        g_part[blockIdx.x] = (sp[0] + sp[1]) + (sp[2] + sp[3]);
        __threadfence();
        unsigned r = atomicAdd(&g_cnt, 1u);
        is_last = (r == gridDim.x - 1);
    }
    __syncthreads();
    if (is_last) {
        __threadfence();
        double ds = 0.0;
#pragma unroll
        for (int i = threadIdx.x; i < 1024; i += 128) ds += (double)g_part[i];
        sh[threadIdx.x] = ds;
        __syncthreads();
        for (int o = 64; o > 0; o >>= 1) {
            if (threadIdx.x < o) sh[threadIdx.x] += sh[threadIdx.x + o];
            __syncthreads();
        }
        if (threadIdx.x == 0) {
            out[0] = (float)(sh[0] * (1.0 / 252004.0));
            g_cnt = 0;   // reset for next graph replay (deterministic)
        }
    }
}

extern "C" void kernel_launch(void* const* d_in, const int* in_sizes, int n_in,
                              void* d_out, int out_size) {
    const float* X = (const float*)d_in[0];
    const float* Y = (const float*)d_in[1];
    float* out = (float*)d_out;

    // 4096 warps = 64 images x 4 col-stripes(128) x 16 row-strips(32); 4/block
    loss_kernel<<<1024, 128>>>(X, Y, out);
}